// round 4
// baseline (speedup 1.0000x reference)
#include <cuda_runtime.h>

// AutoregressiveBisectionInverter — closed-form inversion, latency-optimized R4.
//
// W strictly lower triangular => bisected function is linear in x_i:
//   x_i = (y_i - sum_{j<i} W[i,j] tanh(x_j)) / softplus(a_i)
// Pre-scale: Wsh[i][j] = -W[i,j]/softplus(a_i), y'_i = y_i/softplus(a_i)
//   => x_i = y'_i + sum_{j<i} Wsh[i,j] * tanh(x_j)
//
// R4 changes vs R3:
//  * All global loads (y, W, a) issued up-front and independently — one memory
//    round trip instead of three serialized ones.
//  * softplus via __expf/__logf/__fdividef (MUFU-only, no branchy log1pf).
//  * __launch_bounds__(128,1) frees the register budget; per-chunk diagonal-band
//    W values read into locals early so LDS latency overlaps the tanh chain.

#define AD 64
#define AB 512
#define ROWS_PER_BLOCK 4
#define NTHREADS (32 * ROWS_PER_BLOCK)

__device__ __forceinline__ float tanh_fast(float x) {
    float r;
    asm("tanh.approx.f32 %0, %1;" : "=f"(r) : "f"(x));
    return r;
}

__global__ __launch_bounds__(NTHREADS, 1)
void arbi_kernel(const float* __restrict__ y,
                 const float* __restrict__ a,
                 const float* __restrict__ W,
                 float* __restrict__ out)
{
    __shared__ float invs_sh[AD];
    __shared__ float Wsh[AD * 65];

    const int tid  = threadIdx.x;
    const int lane = tid & 31;
    const int warp = tid >> 5;
    const int row  = blockIdx.x * ROWS_PER_BLOCK + warp;

    // ---- Issue ALL independent global loads first (single round trip) ----
    const float* yr = y + row * AD;
    const float yv0 = yr[lane];
    const float yv1 = yr[lane + 32];

    const float4* W4 = (const float4*)W;
    float4 wv[8];
    #pragma unroll
    for (int k = 0; k < 8; ++k) {
        wv[k] = W4[tid + NTHREADS * k];     // raw W, scaled after sync
    }

    float av = 0.0f;
    if (tid < AD) av = a[tid];

    // ---- softplus inverse (MUFU-only): 1/log(1+e^a) ----
    if (tid < AD) {
        invs_sh[tid] = __fdividef(1.0f, __logf(1.0f + __expf(av)));
    }
    __syncthreads();

    // ---- Scale staged W in registers, store to padded smem ----
    #pragma unroll
    for (int k = 0; k < 8; ++k) {
        const int idx = tid + NTHREADS * k;   // float4 index; 16 per row
        const int r   = idx >> 4;
        const int c4  = idx & 15;
        const float sc = -invs_sh[r];
        float* dst = &Wsh[r * 65 + c4 * 4];
        dst[0] = wv[k].x * sc; dst[1] = wv[k].y * sc;
        dst[2] = wv[k].z * sc; dst[3] = wv[k].w * sc;
    }
    __syncthreads();

    // ---- Per-lane scaled targets ----
    float acc0 = yv0 * invs_sh[lane];
    float acc1 = yv1 * invs_sh[lane + 32];
    float out0 = 0.0f, out1 = 0.0f;

    // Chunk 0 partials: dims 0..3 live in acc0 of lanes 0..3.
    float b0 = __shfl_sync(0xffffffffu, acc0, 0);
    float b1 = __shfl_sync(0xffffffffu, acc0, 1);
    float b2 = __shfl_sync(0xffffffffu, acc0, 2);
    float b3 = __shfl_sync(0xffffffffu, acc0, 3);

    #pragma unroll
    for (int c = 0; c < 16; ++c) {
        const int j = 4 * c;

        // Early reads of all lane-uniform diagonal-band values for this chunk
        // (static smem addresses -> LDS latency overlaps the tanh chain).
        const float w10 = Wsh[(j + 1) * 65 + j];
        const float w20 = Wsh[(j + 2) * 65 + j];
        const float w21 = Wsh[(j + 2) * 65 + j + 1];
        const float w30 = Wsh[(j + 3) * 65 + j];
        const float w31 = Wsh[(j + 3) * 65 + j + 1];
        const float w32 = Wsh[(j + 3) * 65 + j + 2];
        float w42 = 0.f, w43 = 0.f, w52 = 0.f, w53 = 0.f;
        float w62 = 0.f, w63 = 0.f, w72 = 0.f, w73 = 0.f;
        if (c < 15) {
            w42 = Wsh[(j + 4) * 65 + j + 2]; w43 = Wsh[(j + 4) * 65 + j + 3];
            w52 = Wsh[(j + 5) * 65 + j + 2]; w53 = Wsh[(j + 5) * 65 + j + 3];
            w62 = Wsh[(j + 6) * 65 + j + 2]; w63 = Wsh[(j + 6) * 65 + j + 3];
            w72 = Wsh[(j + 7) * 65 + j + 2]; w73 = Wsh[(j + 7) * 65 + j + 3];
        }
        // Per-lane acc-update weights for the 4 columns of this chunk.
        const float wl0a = Wsh[lane * 65 + j];
        const float wl0b = Wsh[(lane + 32) * 65 + j];
        const float wl1a = Wsh[lane * 65 + j + 1];
        const float wl1b = Wsh[(lane + 32) * 65 + j + 1];
        const float wl2a = Wsh[lane * 65 + j + 2];
        const float wl2b = Wsh[(lane + 32) * 65 + j + 2];
        const float wl3a = Wsh[lane * 65 + j + 3];
        const float wl3b = Wsh[(lane + 32) * 65 + j + 3];

        // ---- dim j ----
        const float x0 = b0;
        const float t0 = tanh_fast(x0);
        if (j < 32) out0 = (lane == j)      ? x0 : out0;
        else        out1 = (lane == j - 32) ? x0 : out1;

        // ---- dim j+1 ----
        const float x1 = fmaf(w10, t0, b1);
        const float t1 = tanh_fast(x1);
        if (j + 1 < 32) out0 = (lane == j + 1)      ? x1 : out0;
        else            out1 = (lane == j + 1 - 32) ? x1 : out1;

        acc0 = fmaf(wl0a, t0, acc0);
        acc1 = fmaf(wl0b, t0, acc1);
        acc0 = fmaf(wl1a, t1, acc0);
        acc1 = fmaf(wl1b, t1, acc1);

        // Early shfl of next chunk's partials (contain t_{<=j+1}); the missing
        // t_{j+2}, t_{j+3} updates are replayed on all lanes below.
        float bp0 = 0.f, bp1 = 0.f, bp2 = 0.f, bp3 = 0.f;
        if (c < 15) {
            const float src = (j + 4 < 32) ? acc0 : acc1;
            bp0 = __shfl_sync(0xffffffffu, src, (j + 4) & 31);
            bp1 = __shfl_sync(0xffffffffu, src, (j + 5) & 31);
            bp2 = __shfl_sync(0xffffffffu, src, (j + 6) & 31);
            bp3 = __shfl_sync(0xffffffffu, src, (j + 7) & 31);
        }

        // ---- dim j+2 ----
        const float x2 = fmaf(w21, t1, fmaf(w20, t0, b2));
        const float t2 = tanh_fast(x2);
        if (j + 2 < 32) out0 = (lane == j + 2)      ? x2 : out0;
        else            out1 = (lane == j + 2 - 32) ? x2 : out1;

        acc0 = fmaf(wl2a, t2, acc0);
        acc1 = fmaf(wl2b, t2, acc1);

        // ---- dim j+3 ----
        const float x3 = fmaf(w32, t2, fmaf(w31, t1, fmaf(w30, t0, b3)));
        const float t3 = tanh_fast(x3);
        if (j + 3 < 32) out0 = (lane == j + 3)      ? x3 : out0;
        else            out1 = (lane == j + 3 - 32) ? x3 : out1;

        acc0 = fmaf(wl3a, t3, acc0);
        acc1 = fmaf(wl3b, t3, acc1);

        // Replay t_{j+2}, t_{j+3} into the early-shfl'd partials.
        if (c < 15) {
            b0 = fmaf(w43, t3, fmaf(w42, t2, bp0));
            b1 = fmaf(w53, t3, fmaf(w52, t2, bp1));
            b2 = fmaf(w63, t3, fmaf(w62, t2, bp2));
            b3 = fmaf(w73, t3, fmaf(w72, t2, bp3));
        }
    }

    // Coalesced store.
    out[row * AD + lane]      = out0;
    out[row * AD + lane + 32] = out1;
}

extern "C" void kernel_launch(void* const* d_in, const int* in_sizes, int n_in,
                              void* d_out, int out_size)
{
    const float* y = (const float*)d_in[0];   // (512, 64)
    const float* a = (const float*)d_in[1];   // (64,)
    const float* W = (const float*)d_in[2];   // (64, 64)
    float* out = (float*)d_out;               // (512, 64)

    arbi_kernel<<<AB / ROWS_PER_BLOCK, NTHREADS>>>(y, a, W, out);
}